// round 1
// baseline (speedup 1.0000x reference)
#include <cuda_runtime.h>
#include <math.h>

#define EPS 1e-8f

// Per-op weights computed on device from param (softmax over op axis, summed over N=16).
__device__ float g_w[6];

__global__ void compute_weights_kernel(const float* __restrict__ param) {
    // param is [6, 16] row-major. Single thread: 96 values, trivial.
    if (threadIdx.x == 0 && blockIdx.x == 0) {
        float w[6];
        #pragma unroll
        for (int i = 0; i < 6; i++) w[i] = 0.0f;
        for (int j = 0; j < 16; j++) {
            float v[6];
            float m = -1e30f;
            #pragma unroll
            for (int i = 0; i < 6; i++) {
                v[i] = param[i * 16 + j];
                m = fmaxf(m, v[i]);
            }
            float s = 0.0f;
            float e[6];
            #pragma unroll
            for (int i = 0; i < 6; i++) {
                e[i] = expf(v[i] - m);
                s += e[i];
            }
            float inv = 1.0f / s;
            #pragma unroll
            for (int i = 0; i < 6; i++) w[i] += e[i] * inv;
        }
        #pragma unroll
        for (int i = 0; i < 6; i++) g_w[i] = w[i];
    }
}

__device__ __forceinline__ float fuse_op(float x, float y,
                                         float w0, float w1, float w2,
                                         float w3, float w4, float w5) {
    float ax = fabsf(x);
    float ay = fabsf(y);
    float r = w0 * (x + y);
    r += w1 * (x * y);
    r += w2 * (x / (ay + EPS));
    r += w3 * (y / (ax + EPS));
    r += w4 * (x * sinf(y));
    r += w5 * (y * sinf(x));
    return r;
}

__global__ void __launch_bounds__(256)
fused_elementwise_kernel(const float4* __restrict__ x4,
                         const float4* __restrict__ y4,
                         float4* __restrict__ out4,
                         long long n4) {
    long long idx = (long long)blockIdx.x * blockDim.x + threadIdx.x;
    if (idx >= n4) return;

    // Broadcast weight loads — L1/L2 cached, same address across all threads.
    float w0 = g_w[0], w1 = g_w[1], w2 = g_w[2];
    float w3 = g_w[3], w4 = g_w[4], w5 = g_w[5];

    float4 xv = x4[idx];
    float4 yv = y4[idx];
    float4 o;
    o.x = fuse_op(xv.x, yv.x, w0, w1, w2, w3, w4, w5);
    o.y = fuse_op(xv.y, yv.y, w0, w1, w2, w3, w4, w5);
    o.z = fuse_op(xv.z, yv.z, w0, w1, w2, w3, w4, w5);
    o.w = fuse_op(xv.w, yv.w, w0, w1, w2, w3, w4, w5);
    out4[idx] = o;
}

// Scalar tail kernel (n not divisible by 4 — not expected here, but safe).
__global__ void fused_tail_kernel(const float* __restrict__ x,
                                  const float* __restrict__ y,
                                  float* __restrict__ out,
                                  long long start, long long n) {
    long long idx = start + (long long)blockIdx.x * blockDim.x + threadIdx.x;
    if (idx >= n) return;
    float w0 = g_w[0], w1 = g_w[1], w2 = g_w[2];
    float w3 = g_w[3], w4 = g_w[4], w5 = g_w[5];
    out[idx] = fuse_op(x[idx], y[idx], w0, w1, w2, w3, w4, w5);
}

extern "C" void kernel_launch(void* const* d_in, const int* in_sizes, int n_in,
                              void* d_out, int out_size) {
    const float* x = (const float*)d_in[0];
    const float* y = (const float*)d_in[1];
    const float* param = (const float*)d_in[2];
    float* out = (float*)d_out;

    long long n = (long long)in_sizes[0];  // 4*4096*4096 = 67108864
    long long n4 = n / 4;
    long long tail_start = n4 * 4;

    compute_weights_kernel<<<1, 32>>>(param);

    const int threads = 256;
    long long blocks = (n4 + threads - 1) / threads;
    fused_elementwise_kernel<<<(unsigned)blocks, threads>>>(
        (const float4*)x, (const float4*)y, (float4*)out, n4);

    if (tail_start < n) {
        long long tail = n - tail_start;
        long long tblocks = (tail + threads - 1) / threads;
        fused_tail_kernel<<<(unsigned)tblocks, threads>>>(x, y, out, tail_start, n);
    }
}

// round 2
// speedup vs baseline: 1.6694x; 1.6694x over previous
#include <cuda_runtime.h>
#include <math.h>

#define EPS 1e-8f

// Per-op weights computed on device from param (softmax over op axis, summed over N=16).
__device__ float g_w[6];

__global__ void compute_weights_kernel(const float* __restrict__ param) {
    if (threadIdx.x == 0 && blockIdx.x == 0) {
        float w[6];
        #pragma unroll
        for (int i = 0; i < 6; i++) w[i] = 0.0f;
        for (int j = 0; j < 16; j++) {
            float v[6];
            float m = -1e30f;
            #pragma unroll
            for (int i = 0; i < 6; i++) {
                v[i] = param[i * 16 + j];
                m = fmaxf(m, v[i]);
            }
            float s = 0.0f;
            float e[6];
            #pragma unroll
            for (int i = 0; i < 6; i++) {
                e[i] = expf(v[i] - m);
                s += e[i];
            }
            float inv = 1.0f / s;
            #pragma unroll
            for (int i = 0; i < 6; i++) w[i] += e[i] * inv;
        }
        #pragma unroll
        for (int i = 0; i < 6; i++) g_w[i] = w[i];
    }
}

__device__ __forceinline__ float fuse_op(float x, float y,
                                         float w0, float w1, float w2,
                                         float w3, float w4, float w5) {
    float ax = fabsf(x);
    float ay = fabsf(y);
    // MUFU-based fast paths: inputs ~N(0,1); abs err ~1e-5 << 1e-3 tolerance.
    float sy = __sinf(y);
    float sx = __sinf(x);
    float d1 = __fdividef(x, ay + EPS);   // MUFU.RCP + FMUL
    float d2 = __fdividef(y, ax + EPS);
    float r = w0 * (x + y);
    r = fmaf(w1, x * y, r);
    r = fmaf(w2, d1, r);
    r = fmaf(w3, d2, r);
    r = fmaf(w4, x * sy, r);
    r = fmaf(w5, y * sx, r);
    return r;
}

__global__ void __launch_bounds__(256)
fused_elementwise_kernel(const float4* __restrict__ x4,
                         const float4* __restrict__ y4,
                         float4* __restrict__ out4,
                         long long n4) {
    long long idx = (long long)blockIdx.x * blockDim.x + threadIdx.x;
    if (idx >= n4) return;

    float w0 = g_w[0], w1 = g_w[1], w2 = g_w[2];
    float w3 = g_w[3], w4 = g_w[4], w5 = g_w[5];

    // Streaming loads/stores: no reuse, evict-first to keep L2 clean.
    float4 xv = __ldcs(&x4[idx]);
    float4 yv = __ldcs(&y4[idx]);
    float4 o;
    o.x = fuse_op(xv.x, yv.x, w0, w1, w2, w3, w4, w5);
    o.y = fuse_op(xv.y, yv.y, w0, w1, w2, w3, w4, w5);
    o.z = fuse_op(xv.z, yv.z, w0, w1, w2, w3, w4, w5);
    o.w = fuse_op(xv.w, yv.w, w0, w1, w2, w3, w4, w5);
    __stcs(&out4[idx], o);
}

// Scalar tail kernel (n not divisible by 4 — not expected here, but safe).
__global__ void fused_tail_kernel(const float* __restrict__ x,
                                  const float* __restrict__ y,
                                  float* __restrict__ out,
                                  long long start, long long n) {
    long long idx = start + (long long)blockIdx.x * blockDim.x + threadIdx.x;
    if (idx >= n) return;
    float w0 = g_w[0], w1 = g_w[1], w2 = g_w[2];
    float w3 = g_w[3], w4 = g_w[4], w5 = g_w[5];
    out[idx] = fuse_op(x[idx], y[idx], w0, w1, w2, w3, w4, w5);
}

extern "C" void kernel_launch(void* const* d_in, const int* in_sizes, int n_in,
                              void* d_out, int out_size) {
    const float* x = (const float*)d_in[0];
    const float* y = (const float*)d_in[1];
    const float* param = (const float*)d_in[2];
    float* out = (float*)d_out;

    long long n = (long long)in_sizes[0];  // 4*4096*4096 = 67108864
    long long n4 = n / 4;
    long long tail_start = n4 * 4;

    compute_weights_kernel<<<1, 32>>>(param);

    const int threads = 256;
    long long blocks = (n4 + threads - 1) / threads;
    fused_elementwise_kernel<<<(unsigned)blocks, threads>>>(
        (const float4*)x, (const float4*)y, (float4*)out, n4);

    if (tail_start < n) {
        long long tail = n - tail_start;
        long long tblocks = (tail + threads - 1) / threads;
        fused_tail_kernel<<<(unsigned)tblocks, threads>>>(x, y, out, tail_start, n);
    }
}